// round 16
// baseline (speedup 1.0000x reference)
#include <cuda_runtime.h>
#include <math.h>

#define S 2048
#define B 64
#define H 1024
#define NSPLIT 4     // CTAs per batch element in phase 1
#define WPB 8        // warps per block
#define NSK1 8       // k-splits fc1 (grid 16x8 = 128 CTAs, single wave)
#define NSK2 8       // k-splits fc2

// ---------------- scratch (device globals; no allocation) ----------------
__device__ __align__(16) float g_part_acc[B * NSPLIT * H];
__device__ float g_part_m[B * NSPLIT];
__device__ float g_part_l[B * NSPLIT];
__device__ __align__(16) float g_part1T[NSK1 * H * B];   // [split][j][b]
__device__ __align__(16) float g_tT[H * B];              // tanh output, [j][b]
__device__ __align__(16) float g_part2[NSK2 * B * H];    // [split][b][j]

// ---------------- phase 1: fused scores + online softmax + weighted sum ----
__global__ __launch_bounds__(256, 2) void k_attn(const float* __restrict__ ctx,
                                                 const float* __restrict__ key,
                                                 const float* __restrict__ mask,
                                                 float* __restrict__ at_raw)
{
    const int b    = blockIdx.y;
    const int warp = threadIdx.x >> 5;
    const int lane = threadIdx.x & 31;
    const int wg   = blockIdx.x * WPB + warp;   // 0..31 warp-slots per b

    __shared__ float4 s_key[H / 4];             // 4KB
    __shared__ float4 s_acc[WPB][H / 4];        // 32KB combine buffer
    __shared__ float  s_m[WPB], s_l[WPB];

    s_key[threadIdx.x] = ((const float4*)(key + b * H))[threadIdx.x];
    __syncthreads();

    float4 acc[8];
#pragma unroll
    for (int k = 0; k < 8; k++) acc[k] = make_float4(0.f, 0.f, 0.f, 0.f);
    float m = -3.0e38f, l = 0.f;

    const int NW = NSPLIT * WPB;  // 32
#pragma unroll 1
    for (int s = wg; s < S; s += NW) {
        const float4* row = (const float4*)(ctx + ((long)s * B + b) * H);
        float4 c[8];
#pragma unroll
        for (int k = 0; k < 8; k++) c[k] = row[lane + 32 * k];
        float p = 0.f;
#pragma unroll
        for (int k = 0; k < 8; k++) {
            float4 kv = s_key[lane + 32 * k];
            p += c[k].x * kv.x + c[k].y * kv.y + c[k].z * kv.z + c[k].w * kv.w;
        }
#pragma unroll
        for (int off = 16; off >= 1; off >>= 1)
            p += __shfl_xor_sync(0xffffffffu, p, off);
        p += mask[b * S + s];
        if (lane == 0) at_raw[b * S + s] = p;   // raw score, normalized later
        if (p > m) {
            float sc = __expf(m - p);           // first iter: exp(-huge)=0
#pragma unroll
            for (int k = 0; k < 8; k++) {
                acc[k].x *= sc; acc[k].y *= sc; acc[k].z *= sc; acc[k].w *= sc;
            }
            l *= sc;
            m = p;
        }
        float w = __expf(p - m);
        l += w;
#pragma unroll
        for (int k = 0; k < 8; k++) {
            acc[k].x += w * c[k].x; acc[k].y += w * c[k].y;
            acc[k].z += w * c[k].z; acc[k].w += w * c[k].w;
        }
    }

    // CTA-level combine of 8 warp partials
#pragma unroll
    for (int k = 0; k < 8; k++) s_acc[warp][lane + 32 * k] = acc[k];
    if (lane == 0) { s_m[warp] = m; s_l[warp] = l; }
    __syncthreads();

    const int t = threadIdx.x;
    float M = -3.0e38f;
#pragma unroll
    for (int w = 0; w < WPB; w++) M = fmaxf(M, s_m[w]);
    float L = 0.f;
    float4 a = make_float4(0.f, 0.f, 0.f, 0.f);
#pragma unroll
    for (int w = 0; w < WPB; w++) {
        float sc = __expf(s_m[w] - M);
        L += sc * s_l[w];
        float4 v = s_acc[w][t];
        a.x += sc * v.x; a.y += sc * v.y; a.z += sc * v.z; a.w += sc * v.w;
    }
    ((float4*)g_part_acc)[(b * NSPLIT + blockIdx.x) * (H / 4) + t] = a;
    if (t == 0) {
        g_part_m[b * NSPLIT + blockIdx.x] = M;
        g_part_l[b * NSPLIT + blockIdx.x] = L;
    }
}

// ---------------- phase 2: fused finish + fc1 split-K GEMM ------------------
// A(64 x 2048) built on the fly: k<1024 -> combined attn, k>=1024 -> key.
// C_part written transposed: g_part1T[split][j][b].
__global__ __launch_bounds__(256) void k_fc1f(const float* __restrict__ key,
                                              const float* __restrict__ W)
{
    const int K = 2 * H;
    __shared__ float As[32][68];
    __shared__ float Ws[32][68];
    __shared__ float sc_s[B][4];        // per-b combine scales (incl. 1/L)

    const int jb     = blockIdx.x * 64;
    const int ks     = blockIdx.y;                 // 0..7
    const int kbase0 = ks * (K / NSK1);            // 256-wide slice
    const int t  = threadIdx.x;
    const int tx = t & 15, ty = t >> 4;

    if (t < B) {
        float pm[NSPLIT], pl[NSPLIT];
        float M = -3.0e38f;
#pragma unroll
        for (int i = 0; i < NSPLIT; i++) {
            pm[i] = g_part_m[t * NSPLIT + i];
            pl[i] = g_part_l[t * NSPLIT + i];
            M = fmaxf(M, pm[i]);
        }
        float L = 0.f;
#pragma unroll
        for (int i = 0; i < NSPLIT; i++) L += __expf(pm[i] - M) * pl[i];
        float invL = 1.f / L;
#pragma unroll
        for (int i = 0; i < NSPLIT; i++) sc_s[t][i] = __expf(pm[i] - M) * invL;
    }
    __syncthreads();

    float c[4][4];
#pragma unroll
    for (int i = 0; i < 4; i++)
#pragma unroll
        for (int j = 0; j < 4; j++) c[i][j] = 0.f;

#pragma unroll 1
    for (int kb = 0; kb < K / NSK1; kb += 32) {
        const int kbase = kbase0 + kb;
        if (ks < 4) {   // attn region: combine NSPLIT partial accumulators
#pragma unroll
            for (int i = 0; i < 8; i++) {
                int g = t + i * 256;
                int bb = g >> 5, kk = g & 31;
                float v = 0.f;
#pragma unroll
                for (int ii = 0; ii < NSPLIT; ii++)
                    v += sc_s[bb][ii] * g_part_acc[(bb * NSPLIT + ii) * H + kbase + kk];
                As[kk][bb] = v;
            }
        } else {        // key region
#pragma unroll
            for (int i = 0; i < 8; i++) {
                int g = t + i * 256;
                int bb = g >> 5, kk = g & 31;
                As[kk][bb] = key[bb * H + kbase - H + kk];
            }
        }
#pragma unroll
        for (int i = 0; i < 8; i++) {
            int g = t + i * 256;
            Ws[g & 31][g >> 5] = W[(jb + (g >> 5)) * K + kbase + (g & 31)];
        }
        __syncthreads();
#pragma unroll
        for (int kk = 0; kk < 32; kk++) {
            float4 av = *(const float4*)&As[kk][ty * 4];
            float4 wv = *(const float4*)&Ws[kk][tx * 4];
            c[0][0] += av.x * wv.x; c[0][1] += av.x * wv.y; c[0][2] += av.x * wv.z; c[0][3] += av.x * wv.w;
            c[1][0] += av.y * wv.x; c[1][1] += av.y * wv.y; c[1][2] += av.y * wv.z; c[1][3] += av.y * wv.w;
            c[2][0] += av.z * wv.x; c[2][1] += av.z * wv.y; c[2][2] += av.z * wv.z; c[2][3] += av.z * wv.w;
            c[3][0] += av.w * wv.x; c[3][1] += av.w * wv.y; c[3][2] += av.w * wv.z; c[3][3] += av.w * wv.w;
        }
        __syncthreads();
    }
    // transposed store: [split][j][b], float4 over the 4-b fragment
#pragma unroll
    for (int ji = 0; ji < 4; ji++) {
        float4 v = make_float4(c[0][ji], c[1][ji], c[2][ji], c[3][ji]);
        *(float4*)&g_part1T[((long)(ks * H + jb + tx * 4 + ji)) * B + ty * 4] = v;
    }
}

// ---------------- phase 3: reduce splits + bias + BN(train) + tanh ----------
__global__ __launch_bounds__(256) void k_bnf(const float* __restrict__ fc1_b,
                                             const float* __restrict__ gamma,
                                             const float* __restrict__ beta)
{
    const int t  = threadIdx.x;
    const int jj = t >> 6;            // 0..3
    const int b  = t & 63;
    const int j  = blockIdx.x * 4 + jj;

    float y = fc1_b[j];
#pragma unroll
    for (int s2 = 0; s2 < NSK1; s2++)
        y += g_part1T[((long)(s2 * H + j)) * B + b];   // coalesced: b fast

    float s1 = y, s2v = y * y;
#pragma unroll
    for (int off = 16; off >= 1; off >>= 1) {
        s1  += __shfl_xor_sync(0xffffffffu, s1, off);
        s2v += __shfl_xor_sync(0xffffffffu, s2v, off);
    }
    __shared__ float sm1[8], sm2[8];
    const int warp = t >> 5;
    if ((t & 31) == 0) { sm1[warp] = s1; sm2[warp] = s2v; }
    __syncthreads();
    float S1 = sm1[jj * 2] + sm1[jj * 2 + 1];
    float S2 = sm2[jj * 2] + sm2[jj * 2 + 1];
    float mean = S1 * (1.f / 64.f);
    float var  = S2 * (1.f / 64.f) - mean * mean;
    float rstd = rsqrtf(var + 1e-5f);
    g_tT[j * B + b] = tanhf((y - mean) * rstd * gamma[j] + beta[j]);   // coalesced
}

// ---------------- phase 4: fc2 split-K GEMM (A read K-major from g_tT) ------
__global__ __launch_bounds__(256) void k_fc2f(const float* __restrict__ W)
{
    const int K = H;
    __shared__ float As[32][68];
    __shared__ float Ws[32][68];
    const int jb     = blockIdx.x * 64;
    const int ks     = blockIdx.y;              // 0..7
    const int kbase0 = ks * (K / NSK2);         // 128-wide slice
    const int t  = threadIdx.x;
    const int tx = t & 15, ty = t >> 4;

    float c[4][4];
#pragma unroll
    for (int i = 0; i < 4; i++)
#pragma unroll
        for (int j = 0; j < 4; j++) c[i][j] = 0.f;

#pragma unroll 1
    for (int kb = 0; kb < K / NSK2; kb += 32) {
        const int kbase = kbase0 + kb;
#pragma unroll
        for (int i = 0; i < 8; i++) {
            int g = t + i * 256;
            int bb = g & 63, kk = g >> 6;       // coalesced from [j][b]
            As[kk][bb] = g_tT[(kbase + kk) * B + bb];
        }
#pragma unroll
        for (int i = 0; i < 8; i++) {
            int g = t + i * 256;
            Ws[g & 31][g >> 5] = W[(jb + (g >> 5)) * K + kbase + (g & 31)];
        }
        __syncthreads();
#pragma unroll
        for (int kk = 0; kk < 32; kk++) {
            float4 av = *(const float4*)&As[kk][ty * 4];
            float4 wv = *(const float4*)&Ws[kk][tx * 4];
            c[0][0] += av.x * wv.x; c[0][1] += av.x * wv.y; c[0][2] += av.x * wv.z; c[0][3] += av.x * wv.w;
            c[1][0] += av.y * wv.x; c[1][1] += av.y * wv.y; c[1][2] += av.y * wv.z; c[1][3] += av.y * wv.w;
            c[2][0] += av.z * wv.x; c[2][1] += av.z * wv.y; c[2][2] += av.z * wv.z; c[2][3] += av.z * wv.w;
            c[3][0] += av.w * wv.x; c[3][1] += av.w * wv.y; c[3][2] += av.w * wv.z; c[3][3] += av.w * wv.w;
        }
        __syncthreads();
    }
#pragma unroll
    for (int mi = 0; mi < 4; mi++) {
        float4 v = make_float4(c[mi][0], c[mi][1], c[mi][2], c[mi][3]);
        *(float4*)&g_part2[((long)(ks * B + ty * 4 + mi)) * H + jb + tx * 4] = v;
    }
}

// ---------------- phase 5: reduce fc2 partials + bias -> x; normalize At ----
__global__ __launch_bounds__(256) void k_outx(const float* __restrict__ fc2_b,
                                              float* __restrict__ x,
                                              float* __restrict__ at)
{
    const int b  = blockIdx.y;
    const int bx = blockIdx.x;                  // 0..3
    const int t  = threadIdx.x;

    // x output
    const int j = bx * 256 + t;
    float v = fc2_b[j];
#pragma unroll
    for (int s2 = 0; s2 < NSK2; s2++)
        v += g_part2[((long)(s2 * B + b)) * H + j];
    x[b * H + j] = v;

    // At normalization (in place over raw scores)
    float pm[NSPLIT];
    float M = -3.0e38f;
#pragma unroll
    for (int i = 0; i < NSPLIT; i++) {
        pm[i] = g_part_m[b * NSPLIT + i];
        M = fmaxf(M, pm[i]);
    }
    float L = 0.f;
#pragma unroll
    for (int i = 0; i < NSPLIT; i++) L += __expf(pm[i] - M) * g_part_l[b * NSPLIT + i];
    float invL = 1.f / L;
#pragma unroll
    for (int r = 0; r < 2; r++) {
        int s = bx * 512 + r * 256 + t;
        at[b * S + s] = __expf(at[b * S + s] - M) * invL;
    }
}

// ---------------------------------------------------------------------------
extern "C" void kernel_launch(void* const* d_in, const int* in_sizes, int n_in,
                              void* d_out, int out_size)
{
    (void)in_sizes; (void)n_in; (void)out_size;
    const float* ctx   = (const float*)d_in[0];
    const float* key   = (const float*)d_in[1];
    const float* mask  = (const float*)d_in[2];
    const float* fc1_w = (const float*)d_in[3];
    const float* fc1_b = (const float*)d_in[4];
    const float* gamma = (const float*)d_in[5];
    const float* beta  = (const float*)d_in[6];
    const float* fc2_w = (const float*)d_in[7];
    const float* fc2_b = (const float*)d_in[8];

    float* out    = (float*)d_out;
    float* x_out  = out;            // (B, H)
    float* at_out = out + B * H;    // (B, S)

    k_attn <<<dim3(NSPLIT, B), 256>>>(ctx, key, mask, at_out);
    k_fc1f <<<dim3(H / 64, NSK1), 256>>>(key, fc1_w);
    k_bnf  <<<H / 4, 256>>>(fc1_b, gamma, beta);
    k_fc2f <<<dim3(H / 64, NSK2), 256>>>(fc2_w);
    k_outx <<<dim3(4, B), 256>>>(fc2_b, x_out, at_out);
}

// round 17
// speedup vs baseline: 1.0165x; 1.0165x over previous
#include <cuda_runtime.h>
#include <math.h>

#define S 2048
#define B 64
#define H 1024
#define NSPLIT 9        // attention splits per b  -> 9*64 = 576 CTAs
#define WPB 4           // warps per CTA (128 threads)
#define NCTA 576
#define NSK 16          // k-splits for both GEMMs

// ---------------- scratch (device globals; no allocation) ----------------
__device__ __align__(16) float g_part_acc[B * NSPLIT * H];
__device__ float g_part_m[B * NSPLIT];
__device__ float g_part_l[B * NSPLIT];
__device__ __align__(16) float g_xin[B * 2 * H];     // [attn | key], (64, 2048)
__device__ __align__(16) float g_p1[NSK * H * B];    // fc1 partials, [ks][j][b]
__device__ __align__(16) float g_tT[H * B];          // tanh out, [j][b]
__device__ __align__(16) float g_p2[NSK * B * H];    // fc2 partials, [ks][b][j]
__device__ unsigned g_bar_count;                     // zero-init, self-restoring
__device__ unsigned g_bar_phase;                     // monotonic

// Software grid barrier. Safe: all NCTA CTAs are co-resident (occ 4 x 148 SMs
// = 592 slots >= 576). Phase counter is monotonic across graph replays; count
// returns to 0 after every barrier.
__device__ __forceinline__ void grid_barrier()
{
    __syncthreads();
    __threadfence();                       // publish this CTA's writes
    if (threadIdx.x == 0) {
        unsigned ph  = *(volatile unsigned*)&g_bar_phase;
        unsigned old = atomicAdd(&g_bar_count, 1u);
        if (old == NCTA - 1u) {
            atomicExch(&g_bar_count, 0u);
            __threadfence();
            atomicExch(&g_bar_phase, ph + 1u);   // release
        } else {
            while (*(volatile unsigned*)&g_bar_phase == ph) __nanosleep(64);
        }
    }
    __syncthreads();
}

__global__ __launch_bounds__(128, 4)
void k_fused(const float* __restrict__ ctx,  const float* __restrict__ key,
             const float* __restrict__ mask,
             const float* __restrict__ fc1_w, const float* __restrict__ fc1_b,
             const float* __restrict__ gamma, const float* __restrict__ beta,
             const float* __restrict__ fc2_w, const float* __restrict__ fc2_b,
             float* __restrict__ x, float* __restrict__ at)
{
    const int t   = threadIdx.x;
    const int cta = blockIdx.x;

    __shared__ float4 s_key[H / 4];          // 4KB
    __shared__ float4 s_acc[WPB][H / 4];     // 16KB
    __shared__ float  s_m[WPB], s_l[WPB];
    __shared__ float  As[32][68];            // 8.7KB (GEMM A tile / transpose buf)
    __shared__ float  Ws[32][36];            // 4.6KB (GEMM W tile)
    __shared__ float  sred1[4], sred2[4];

    // ================= Phase A: attention partials =================
    {
        const int b     = cta & 63;
        const int split = cta >> 6;               // 0..8
        const int warp  = t >> 5, lane = t & 31;
        const int wg    = split * WPB + warp;     // 0..35

        const float4* key4 = (const float4*)(key + b * H);
        s_key[t]       = key4[t];
        s_key[t + 128] = key4[t + 128];
        __syncthreads();

        float4 acc[8];
#pragma unroll
        for (int k = 0; k < 8; k++) acc[k] = make_float4(0.f, 0.f, 0.f, 0.f);
        float m = -3.0e38f, l = 0.f;

#pragma unroll 1
        for (int s = wg; s < S; s += NSPLIT * WPB) {
            const float4* row = (const float4*)(ctx + ((long)s * B + b) * H);
            float4 c[8];
#pragma unroll
            for (int k = 0; k < 8; k++) c[k] = row[lane + 32 * k];
            float p = 0.f;
#pragma unroll
            for (int k = 0; k < 8; k++) {
                float4 kv = s_key[lane + 32 * k];
                p += c[k].x * kv.x + c[k].y * kv.y + c[k].z * kv.z + c[k].w * kv.w;
            }
#pragma unroll
            for (int off = 16; off >= 1; off >>= 1)
                p += __shfl_xor_sync(0xffffffffu, p, off);
            p += mask[b * S + s];
            if (lane == 0) at[b * S + s] = p;     // raw score
            if (p > m) {
                float sc = __expf(m - p);
#pragma unroll
                for (int k = 0; k < 8; k++) {
                    acc[k].x *= sc; acc[k].y *= sc; acc[k].z *= sc; acc[k].w *= sc;
                }
                l *= sc;
                m = p;
            }
            float w = __expf(p - m);
            l += w;
#pragma unroll
            for (int k = 0; k < 8; k++) {
                acc[k].x += w * c[k].x; acc[k].y += w * c[k].y;
                acc[k].z += w * c[k].z; acc[k].w += w * c[k].w;
            }
        }

#pragma unroll
        for (int k = 0; k < 8; k++) s_acc[warp][lane + 32 * k] = acc[k];
        if (lane == 0) { s_m[warp] = m; s_l[warp] = l; }
        __syncthreads();

        float M = fmaxf(fmaxf(s_m[0], s_m[1]), fmaxf(s_m[2], s_m[3]));
        float sc[WPB];
        float L = 0.f;
#pragma unroll
        for (int w = 0; w < WPB; w++) {
            sc[w] = __expf(s_m[w] - M);
            L += sc[w] * s_l[w];
        }
#pragma unroll
        for (int half = 0; half < 2; half++) {
            int col = t + half * 128;
            float4 a = make_float4(0.f, 0.f, 0.f, 0.f);
#pragma unroll
            for (int w = 0; w < WPB; w++) {
                float4 v = s_acc[w][col];
                a.x += sc[w] * v.x; a.y += sc[w] * v.y;
                a.z += sc[w] * v.z; a.w += sc[w] * v.w;
            }
            ((float4*)g_part_acc)[(b * NSPLIT + split) * (H / 4) + col] = a;
        }
        if (t == 0) {
            g_part_m[b * NSPLIT + split] = M;
            g_part_l[b * NSPLIT + split] = L;
        }
    }
    grid_barrier();

    // ===== Phase B: combine splits -> g_xin (CTAs 0..63); At normalize =====
    if (cta < 64) {
        const int b = cta;
        float pm[NSPLIT], pl[NSPLIT], sc[NSPLIT];
        float M = -3.0e38f;
#pragma unroll
        for (int i = 0; i < NSPLIT; i++) {
            pm[i] = g_part_m[b * NSPLIT + i];
            pl[i] = g_part_l[b * NSPLIT + i];
            M = fmaxf(M, pm[i]);
        }
        float L = 0.f;
#pragma unroll
        for (int i = 0; i < NSPLIT; i++) { sc[i] = __expf(pm[i] - M); L += sc[i] * pl[i]; }
        float invL = 1.f / L;
#pragma unroll
        for (int i = 0; i < NSPLIT; i++) sc[i] *= invL;
#pragma unroll
        for (int half = 0; half < 2; half++) {
            int col = t + half * 128;
            float4 a = make_float4(0.f, 0.f, 0.f, 0.f);
#pragma unroll
            for (int i = 0; i < NSPLIT; i++) {
                float4 v = ((const float4*)g_part_acc)[(b * NSPLIT + i) * (H / 4) + col];
                a.x += sc[i] * v.x; a.y += sc[i] * v.y;
                a.z += sc[i] * v.z; a.w += sc[i] * v.w;
            }
            ((float4*)g_xin)[b * (2 * H / 4) + col] = a;
            ((float4*)g_xin)[b * (2 * H / 4) + 256 + col] = ((const float4*)key)[b * (H / 4) + col];
        }
    } else {
        const int u0 = (cta - 64) * 256;          // 512 CTAs x 256 elems = 64*2048
        const int b  = u0 >> 11;
        const int s0 = u0 & 2047;
        float pm[NSPLIT];
        float M = -3.0e38f;
#pragma unroll
        for (int i = 0; i < NSPLIT; i++) {
            pm[i] = g_part_m[b * NSPLIT + i];
            M = fmaxf(M, pm[i]);
        }
        float L = 0.f;
#pragma unroll
        for (int i = 0; i < NSPLIT; i++) L += __expf(pm[i] - M) * g_part_l[b * NSPLIT + i];
        float invL = 1.f / L;
#pragma unroll
        for (int r = 0; r < 2; r++) {
            int s = s0 + r * 128 + t;
            at[b * S + s] = __expf(at[b * S + s] - M) * invL;
        }
    }
    grid_barrier();

    // ================= Phase C: fc1 split-K GEMM =================
    // 512 CTAs: jtile 32 (x32) x ks (x16). Output transposed [ks][j][b].
    if (cta < 512) {
        const int jb     = (cta & 31) * 32;
        const int ks     = cta >> 5;               // 0..15
        const int kbase0 = ks * 128;               // K = 2048
        const int tx = t & 7, ty = t >> 3;         // j/4, b/4
        float c[4][4];
#pragma unroll
        for (int i = 0; i < 4; i++)
#pragma unroll
            for (int j = 0; j < 4; j++) c[i][j] = 0.f;

#pragma unroll 1
        for (int kb = 0; kb < 128; kb += 32) {
            const int kbase = kbase0 + kb;
#pragma unroll
            for (int i = 0; i < 16; i++) {
                int g = t + i * 128;
                As[g & 31][g >> 5] = g_xin[(g >> 5) * (2 * H) + kbase + (g & 31)];
            }
#pragma unroll
            for (int i = 0; i < 8; i++) {
                int g = t + i * 128;
                Ws[g & 31][g >> 5] = fc1_w[(jb + (g >> 5)) * (2 * H) + kbase + (g & 31)];
            }
            __syncthreads();
#pragma unroll
            for (int kk = 0; kk < 32; kk++) {
                float4 av = *(const float4*)&As[kk][ty * 4];
                float4 wv = *(const float4*)&Ws[kk][tx * 4];
                c[0][0] += av.x * wv.x; c[0][1] += av.x * wv.y; c[0][2] += av.x * wv.z; c[0][3] += av.x * wv.w;
                c[1][0] += av.y * wv.x; c[1][1] += av.y * wv.y; c[1][2] += av.y * wv.z; c[1][3] += av.y * wv.w;
                c[2][0] += av.z * wv.x; c[2][1] += av.z * wv.y; c[2][2] += av.z * wv.z; c[2][3] += av.z * wv.w;
                c[3][0] += av.w * wv.x; c[3][1] += av.w * wv.y; c[3][2] += av.w * wv.z; c[3][3] += av.w * wv.w;
            }
            __syncthreads();
        }
        // transpose frag through As -> coalesced [ks][j][b] store
#pragma unroll
        for (int jj = 0; jj < 4; jj++)
#pragma unroll
            for (int bi = 0; bi < 4; bi++)
                As[tx * 4 + jj][ty * 4 + bi] = c[bi][jj];
        __syncthreads();
#pragma unroll
        for (int i = 0; i < 16; i++) {
            int g  = t + i * 128;
            int bb = g & 63, jr = g >> 6;          // jr 0..31
            g_p1[(ks * H + jb + jr) * B + bb] = As[jr][bb];
        }
    }
    grid_barrier();

    // ========== Phase D: reduce ks + bias + BN(train) + tanh ==========
    if (cta < 512) {
        const int jy = t >> 6, b = t & 63;
        const int j  = cta * 2 + jy;
        float y = fc1_b[j];
#pragma unroll
        for (int ksi = 0; ksi < NSK; ksi++)
            y += g_p1[(ksi * H + j) * B + b];      // coalesced (b fast)

        float s1 = y, s2 = y * y;
#pragma unroll
        for (int off = 16; off >= 1; off >>= 1) {
            s1 += __shfl_xor_sync(0xffffffffu, s1, off);
            s2 += __shfl_xor_sync(0xffffffffu, s2, off);
        }
        const int warp = t >> 5;
        if ((t & 31) == 0) { sred1[warp] = s1; sred2[warp] = s2; }
        __syncthreads();
        float S1 = sred1[jy * 2] + sred1[jy * 2 + 1];
        float S2 = sred2[jy * 2] + sred2[jy * 2 + 1];
        float mean = S1 * (1.f / 64.f);
        float var  = S2 * (1.f / 64.f) - mean * mean;
        float rstd = rsqrtf(var + 1e-5f);
        g_tT[j * B + b] = tanhf((y - mean) * rstd * gamma[j] + beta[j]);
    }
    grid_barrier();

    // ================= Phase E: fc2 split-K GEMM =================
    if (cta < 512) {
        const int jb     = (cta & 31) * 32;
        const int ks     = cta >> 5;
        const int kbase0 = ks * 64;                // K = 1024
        const int tx = t & 7, ty = t >> 3;
        float c[4][4];
#pragma unroll
        for (int i = 0; i < 4; i++)
#pragma unroll
            for (int j = 0; j < 4; j++) c[i][j] = 0.f;

#pragma unroll 1
        for (int kb = 0; kb < 64; kb += 32) {
            const int kbase = kbase0 + kb;
#pragma unroll
            for (int i = 0; i < 16; i++) {
                int g = t + i * 128;
                As[g >> 6][g & 63] = g_tT[(kbase + (g >> 6)) * B + (g & 63)];
            }
#pragma unroll
            for (int i = 0; i < 8; i++) {
                int g = t + i * 128;
                Ws[g & 31][g >> 5] = fc2_w[(jb + (g >> 5)) * H + kbase + (g & 31)];
            }
            __syncthreads();
#pragma unroll
            for (int kk = 0; kk < 32; kk++) {
                float4 av = *(const float4*)&As[kk][ty * 4];
                float4 wv = *(const float4*)&Ws[kk][tx * 4];
                c[0][0] += av.x * wv.x; c[0][1] += av.x * wv.y; c[0][2] += av.x * wv.z; c[0][3] += av.x * wv.w;
                c[1][0] += av.y * wv.x; c[1][1] += av.y * wv.y; c[1][2] += av.y * wv.z; c[1][3] += av.y * wv.w;
                c[2][0] += av.z * wv.x; c[2][1] += av.z * wv.y; c[2][2] += av.z * wv.z; c[2][3] += av.z * wv.w;
                c[3][0] += av.w * wv.x; c[3][1] += av.w * wv.y; c[3][2] += av.w * wv.z; c[3][3] += av.w * wv.w;
            }
            __syncthreads();
        }
#pragma unroll
        for (int bi = 0; bi < 4; bi++) {
            float4 v = make_float4(c[bi][0], c[bi][1], c[bi][2], c[bi][3]);
            *(float4*)&g_p2[(ks * B + ty * 4 + bi) * H + jb + tx * 4] = v;
        }
    }
    grid_barrier();

    // ================= Phase F: reduce fc2 partials + bias -> x =========
    if (cta < 512) {
        const int idx = cta * 128 + t;             // < 65536
        const int b = idx >> 10, j = idx & 1023;
        float v = fc2_b[j];
#pragma unroll
        for (int ksi = 0; ksi < NSK; ksi++)
            v += g_p2[(ksi * B + b) * H + j];      // coalesced (j fast)
        x[b * H + j] = v;
    }
}

// ---------------------------------------------------------------------------
extern "C" void kernel_launch(void* const* d_in, const int* in_sizes, int n_in,
                              void* d_out, int out_size)
{
    (void)in_sizes; (void)n_in; (void)out_size;
    const float* ctx   = (const float*)d_in[0];
    const float* key   = (const float*)d_in[1];
    const float* mask  = (const float*)d_in[2];
    const float* fc1_w = (const float*)d_in[3];
    const float* fc1_b = (const float*)d_in[4];
    const float* gamma = (const float*)d_in[5];
    const float* beta  = (const float*)d_in[6];
    const float* fc2_w = (const float*)d_in[7];
    const float* fc2_b = (const float*)d_in[8];

    float* out    = (float*)d_out;
    float* x_out  = out;            // (B, H)
    float* at_out = out + B * H;    // (B, S)

    k_fused<<<NCTA, 128>>>(ctx, key, mask, fc1_w, fc1_b, gamma, beta,
                           fc2_w, fc2_b, x_out, at_out);
}